// round 15
// baseline (speedup 1.0000x reference)
#include <cuda_runtime.h>
#include <cuda_bf16.h>
#include <cstdint>
#include <math.h>

#define BATCH  256
#define SEQ    64
#define DMODEL 512
#define HDIM   512
#define NHEAD  8
#define DK     64
#define EPS_F  1e-7f

#define OUT_ELEMS  (BATCH * SEQ * DMODEL)          // 8388608
#define ATTN_ELEMS (NHEAD * BATCH * SEQ * SEQ)     // 8388608
#define ATTN_OFF   OUT_ELEMS
#define SCALAR_OFF (OUT_ELEMS + ATTN_ELEMS)

#define NROWS  (BATCH * SEQ)   // 16384
#define KPACK  256             // packed bf16x2 pairs per 512-wide row
#define UF     (DMODEL * KPACK / 2)   // 65536 float4-units per weight tensor

// Scratch (device globals; allocation-free per harness rules)
__device__ float    g_vh[NROWS * HDIM];       // V projection (fp32, for sparse P.V)
__device__ uint32_t g_qH[NROWS * KPACK];      // packed Q projection (hi)
__device__ uint32_t g_qL[NROWS * KPACK];
__device__ uint32_t g_kH[NROWS * KPACK];      // packed K projection
__device__ uint32_t g_kL[NROWS * KPACK];
__device__ uint32_t g_oH[NROWS * KPACK];      // packed attention output
__device__ uint32_t g_oL[NROWS * KPACK];
__device__ uint32_t g_fH[DMODEL * KPACK];     // packed fc_w
__device__ uint32_t g_fL[DMODEL * KPACK];
__device__ uint32_t g_gH[DMODEL * KPACK];     // packed gate_w
__device__ uint32_t g_gL[DMODEL * KPACK];
__device__ int      g_cnt_attn[128];          // per out-m-tile dep counter (target 16)

// ---------------------------------------------------------------------------
// Helpers
// ---------------------------------------------------------------------------
__device__ __forceinline__ void bsplit2(float x, float y, uint32_t& h, uint32_t& l) {
    __nv_bfloat162 hp = __floats2bfloat162_rn(x, y);
    float lx = x - __low2float(hp);
    float ly = y - __high2float(hp);
    __nv_bfloat162 lp = __floats2bfloat162_rn(lx, ly);
    h = *reinterpret_cast<uint32_t*>(&hp);
    l = *reinterpret_cast<uint32_t*>(&lp);
}
__device__ __forceinline__ void mma_bf16(float* c, const uint32_t* a, const uint32_t* b) {
    asm volatile(
        "mma.sync.aligned.m16n8k16.row.col.f32.bf16.bf16.f32 "
        "{%0,%1,%2,%3}, {%4,%5,%6,%7}, {%8,%9}, {%0,%1,%2,%3};"
        : "+f"(c[0]), "+f"(c[1]), "+f"(c[2]), "+f"(c[3])
        : "r"(a[0]), "r"(a[1]), "r"(a[2]), "r"(a[3]), "r"(b[0]), "r"(b[1]));
}
__device__ __forceinline__ uint32_t smem_u32(const void* p) {
    uint32_t a;
    asm("{ .reg .u64 t; cvta.to.shared.u64 t, %1; cvt.u32.u64 %0, t; }" : "=r"(a) : "l"(p));
    return a;
}
__device__ __forceinline__ void cp16(uint32_t s, const void* g) {
    asm volatile("cp.async.cg.shared.global [%0], [%1], 16;" :: "r"(s), "l"(g));
}
__device__ __forceinline__ void cp_commit() { asm volatile("cp.async.commit_group;"); }
__device__ __forceinline__ void cp_wait0()  { asm volatile("cp.async.wait_group 0;"); }

// Order-preserving integer key for arbitrary-sign floats (no NaN in data)
__device__ __forceinline__ uint32_t fkey(float f) {
    uint32_t b = __float_as_uint(f);
    return b ^ (uint32_t)(((int32_t)b >> 31) | 0x80000000);
}
__device__ __forceinline__ float funkey(uint32_t k) {
    uint32_t b = (k & 0x80000000u) ? (k ^ 0x80000000u) : ~k;
    return __uint_as_float(b);
}

#define PA   12    // packed A pitch (uint32): frag bank 12g+t conflict-free
#define PBP  136   // proj B [kp][o] pitch: frag bank 8t+g conflict-free

// ---------------------------------------------------------------------------
// Kernel A: group-linear projections + weight-pack tail CTAs (R14, 296us).
//   bid < 1536: proj tile; bid >= 1536: fc/gate weight pack.
//   bid == 1536 also resets the attn->out dependency counters for this launch.
// grid = 2048, block = 256
// ---------------------------------------------------------------------------
__global__ __launch_bounds__(256, 2) void proj_pack(
    const float* __restrict__ q, const float* __restrict__ kin, const float* __restrict__ v,
    const float* __restrict__ Wq, const float* __restrict__ Wk, const float* __restrict__ Wv,
    const float* __restrict__ fw, const float* __restrict__ gww)
{
    __shared__ __align__(16) uint32_t Ahi[128 * PA], Alo[128 * PA];   // [m][kpair]
    __shared__ __align__(16) uint32_t Bhi[8 * PBP],  Blo[8 * PBP];    // [kpair][o]

    const int bid = blockIdx.x;
    const int tid = threadIdx.x;

    if (bid >= 1536) {   // weight-pack role: 512 blocks cover 2*UF float4 units
        if (bid == 1536 && tid < 128) g_cnt_attn[tid] = 0;   // reset dep counters
        int gid = (bid - 1536) * 256 + tid;
        const float* src; uint32_t* H; uint32_t* L; int off;
        if (gid < UF) { src = fw;  H = g_fH; L = g_fL; off = gid; }
        else          { src = gww; H = g_gH; L = g_gL; off = gid - UF; }
        float4 f = ((const float4*)src)[off];
        uint2 h, l;
        bsplit2(f.x, f.y, h.x, l.x);
        bsplit2(f.z, f.w, h.y, l.y);
        ((uint2*)H)[off] = h;
        ((uint2*)L)[off] = l;
        return;
    }

    const int m0 = (bid & 1) * 128;
    const int t2 = bid >> 1;
    const int o0 = (t2 & 3) * 128;
    const int z  = t2 >> 2;
    const int proj = z >> 6, n = z & 63;
    const float* X; const float* W;
    if (proj == 0)      { X = q;   W = Wq; }
    else if (proj == 1) { X = kin; W = Wk; }
    else                { X = v;   W = Wv; }

    const int lane = tid & 31;
    const int wid  = tid >> 5;
    const int g    = lane >> 2;
    const int t    = lane & 3;
    const int warp_m = (wid & 1) * 64;
    const int warp_n = (wid >> 1) * 32;

    const int ar = tid >> 1, sA = (tid & 1);
    const int kp = tid >> 5, og = lane * 4;

    float acc[4][4][4] = {};

    for (int it = 0; it < 32; ++it) {
        const int k0 = it * 16;

        {
            const float* ap = X + (size_t)(m0 + ar) * (SEQ * DMODEL) + (size_t)n * DMODEL + k0 + sA * 8;
            float4 f0 = *(const float4*)ap;
            float4 f1 = *(const float4*)(ap + 4);
            uint4 H, L;
            bsplit2(f0.x, f0.y, H.x, L.x);
            bsplit2(f0.z, f0.w, H.y, L.y);
            bsplit2(f1.x, f1.y, H.z, L.z);
            bsplit2(f1.z, f1.w, H.w, L.w);
            *(uint4*)&Ahi[ar * PA + sA * 4] = H;
            *(uint4*)&Alo[ar * PA + sA * 4] = L;
        }
        {
            const float* bp = W + (size_t)n * (DMODEL * HDIM) + (size_t)(k0 + 2 * kp) * HDIM + o0 + og;
            float4 f0 = *(const float4*)bp;
            float4 f1 = *(const float4*)(bp + HDIM);
            uint4 H, L;
            bsplit2(f0.x, f1.x, H.x, L.x);
            bsplit2(f0.y, f1.y, H.y, L.y);
            bsplit2(f0.z, f1.z, H.z, L.z);
            bsplit2(f0.w, f1.w, H.w, L.w);
            *(uint4*)&Bhi[kp * PBP + og] = H;
            *(uint4*)&Blo[kp * PBP + og] = L;
        }
        __syncthreads();

        uint32_t af[4][4], bh[4][2], bx[4][2];
        #pragma unroll
        for (int mi = 0; mi < 4; ++mi) {
            const int rb = warp_m + mi * 16;
            af[mi][0] = Ahi[(rb + g)     * PA + t];
            af[mi][1] = Ahi[(rb + g + 8) * PA + t];
            af[mi][2] = Ahi[(rb + g)     * PA + t + 4];
            af[mi][3] = Ahi[(rb + g + 8) * PA + t + 4];
        }
        #pragma unroll
        for (int ni = 0; ni < 4; ++ni) {
            const int nb = warp_n + ni * 8;
            bh[ni][0] = Bhi[t       * PBP + nb + g];
            bh[ni][1] = Bhi[(t + 4) * PBP + nb + g];
        }
        #pragma unroll
        for (int mi = 0; mi < 4; ++mi)
            #pragma unroll
            for (int ni = 0; ni < 4; ++ni)
                mma_bf16(acc[mi][ni], af[mi], bh[ni]);    // hi*hi

        #pragma unroll
        for (int ni = 0; ni < 4; ++ni) {
            const int nb = warp_n + ni * 8;
            bx[ni][0] = Blo[t       * PBP + nb + g];
            bx[ni][1] = Blo[(t + 4) * PBP + nb + g];
        }
        #pragma unroll
        for (int mi = 0; mi < 4; ++mi)
            #pragma unroll
            for (int ni = 0; ni < 4; ++ni)
                mma_bf16(acc[mi][ni], af[mi], bx[ni]);    // hi*lo

        #pragma unroll
        for (int mi = 0; mi < 4; ++mi) {
            const int rb = warp_m + mi * 16;
            af[mi][0] = Alo[(rb + g)     * PA + t];
            af[mi][1] = Alo[(rb + g + 8) * PA + t];
            af[mi][2] = Alo[(rb + g)     * PA + t + 4];
            af[mi][3] = Alo[(rb + g + 8) * PA + t + 4];
        }
        #pragma unroll
        for (int mi = 0; mi < 4; ++mi)
            #pragma unroll
            for (int ni = 0; ni < 4; ++ni)
                mma_bf16(acc[mi][ni], af[mi], bh[ni]);    // lo*hi

        __syncthreads();
    }

    if (proj < 2) {
        uint32_t* YH = (proj == 0) ? g_qH : g_kH;
        uint32_t* YL = (proj == 0) ? g_qL : g_kL;
        #pragma unroll
        for (int mi = 0; mi < 4; ++mi) {
            const int r0 = m0 + warp_m + mi * 16 + g;
            #pragma unroll
            for (int ni = 0; ni < 4; ++ni) {
                const int pi = (o0 + warp_n + ni * 8 + 2 * t) >> 1;
                uint32_t h0, l0, h1, l1;
                bsplit2(acc[mi][ni][0], acc[mi][ni][1], h0, l0);
                bsplit2(acc[mi][ni][2], acc[mi][ni][3], h1, l1);
                YH[((size_t)r0 * SEQ + n) * KPACK + pi] = h0;
                YL[((size_t)r0 * SEQ + n) * KPACK + pi] = l0;
                YH[((size_t)(r0 + 8) * SEQ + n) * KPACK + pi] = h1;
                YL[((size_t)(r0 + 8) * SEQ + n) * KPACK + pi] = l1;
            }
        }
    } else {
        #pragma unroll
        for (int mi = 0; mi < 4; ++mi) {
            const int r0 = m0 + warp_m + mi * 16 + g;
            #pragma unroll
            for (int ni = 0; ni < 4; ++ni) {
                const int c0 = o0 + warp_n + ni * 8 + 2 * t;
                *(float2*)(g_vh + ((size_t)r0 * SEQ + n) * HDIM + c0) =
                    make_float2(acc[mi][ni][0], acc[mi][ni][1]);
                *(float2*)(g_vh + ((size_t)(r0 + 8) * SEQ + n) * HDIM + c0) =
                    make_float2(acc[mi][ni][2], acc[mi][ni][3]);
            }
        }
    }
}

// ---------------------------------------------------------------------------
// Kernel B: fused attention + fc/gate with fine-grained interleave.
//   bid%3 != 2 -> attention CTA (2048 total); bid%3 == 2 -> out CTA (1024).
//   out(mx) spins until its 16 attn producer CTAs (earlier bids) signal.
// grid = 3072, block = 256, dyn smem 53248 B
// ---------------------------------------------------------------------------
#define AT_SC  0
#define AT_QH  0
#define AT_QL  2304
#define AT_KH  4608
#define AT_KL  6912
#define AT_V   9216
#define AT_U32 13312
#define AT_BYTES (AT_U32 * 4)
#define QPITCH 36

#define O_AHI(b) ((b) * 6144 + 0)
#define O_ALO(b) ((b) * 6144 + 1536)
#define O_B(b)   ((b) * 6144 + 3072)

__global__ __launch_bounds__(256, 2) void attn_out(
    const float* __restrict__ fc_b, const float* __restrict__ gb,
    float* __restrict__ d_out, int write_attn, int write_scalar)
{
    extern __shared__ uint32_t dsm[];
    const int bid = blockIdx.x;
    const int tid = threadIdx.x;
    const int lane = tid & 31;
    const int wid  = tid >> 5;
    const int g    = lane >> 2;
    const int t    = lane & 3;

    if (bid % 3 != 2) {
        // ================= attention role =================
        const int aidx = (bid / 3) * 2 + (bid % 3);
        const int b  = aidx >> 3;
        const int h  = aidx & 7;

        {
            const int arr = tid >> 6, row = tid & 63;
            const uint32_t* src =
                ((arr == 0) ? g_qH : (arr == 1) ? g_qL : (arr == 2) ? g_kH : g_kL)
                + ((size_t)(b * SEQ + row)) * KPACK + h * 32;
            uint32_t* dst = dsm + ((arr == 0) ? AT_QH : (arr == 1) ? AT_QL
                                   : (arr == 2) ? AT_KH : AT_KL) + row * QPITCH;
            #pragma unroll
            for (int i = 0; i < 8; ++i)
                *(uint4*)(dst + i * 4) = *(const uint4*)(src + i * 4);
        }
        {
            float* vs = (float*)(dsm + AT_V);
            const int vrow = tid >> 2, vq = tid & 3;
            const float* src = g_vh + ((size_t)(b * SEQ + vrow)) * HDIM + h * DK + vq * 16;
            #pragma unroll
            for (int i = 0; i < 4; ++i)
                *(float4*)&vs[vrow * 64 + vq * 16 + i * 4] = *(const float4*)(src + i * 4);
        }
        __syncthreads();

        float acc[4][4] = {};
        const int mb  = (wid >> 1) * 16;
        const int nb0 = (wid & 1) * 32;
        {
            const uint32_t* Qh = dsm + AT_QH;
            const uint32_t* Ql = dsm + AT_QL;
            const uint32_t* Kh = dsm + AT_KH;
            const uint32_t* Kl = dsm + AT_KL;

            #pragma unroll
            for (int c = 0; c < 4; ++c) {
                const int co = c * 8;
                uint32_t aH[4], aL[4], bh[4][2], bl[4][2];
                aH[0] = Qh[(mb + g)     * QPITCH + co + t];
                aH[1] = Qh[(mb + g + 8) * QPITCH + co + t];
                aH[2] = Qh[(mb + g)     * QPITCH + co + t + 4];
                aH[3] = Qh[(mb + g + 8) * QPITCH + co + t + 4];
                aL[0] = Ql[(mb + g)     * QPITCH + co + t];
                aL[1] = Ql[(mb + g + 8) * QPITCH + co + t];
                aL[2] = Ql[(mb + g)     * QPITCH + co + t + 4];
                aL[3] = Ql[(mb + g + 8) * QPITCH + co + t + 4];
                #pragma unroll
                for (int ni = 0; ni < 4; ++ni) {
                    const int nb = nb0 + ni * 8;
                    bh[ni][0] = Kh[(nb + g) * QPITCH + co + t];
                    bh[ni][1] = Kh[(nb + g) * QPITCH + co + t + 4];
                    bl[ni][0] = Kl[(nb + g) * QPITCH + co + t];
                    bl[ni][1] = Kl[(nb + g) * QPITCH + co + t + 4];
                }
                #pragma unroll
                for (int ni = 0; ni < 4; ++ni) {
                    mma_bf16(acc[ni], aH, bh[ni]);
                    mma_bf16(acc[ni], aH, bl[ni]);
                    mma_bf16(acc[ni], aL, bh[ni]);
                }
            }
        }
        __syncthreads();

        {
            float* sc = (float*)(dsm + AT_SC);
            #pragma unroll
            for (int ni = 0; ni < 4; ++ni) {
                const int nb = nb0 + ni * 8;
                *(float2*)&sc[(mb + g) * 66 + nb + 2 * t] =
                    make_float2(acc[ni][0] * 0.125f, acc[ni][1] * 0.125f);
                *(float2*)&sc[(mb + g + 8) * 66 + nb + 2 * t] =
                    make_float2(acc[ni][2] * 0.125f, acc[ni][3] * 0.125f);
            }
        }
        __syncthreads();

        {
            float* sc = (float*)(dsm + AT_SC);
            float* vs = (float*)(dsm + AT_V);
            const unsigned FULL = 0xffffffffu;

            #pragma unroll 2
            for (int rr = 0; rr < 8; rr++) {
                int r = wid * 8 + rr;
                float s0 = sc[r * 66 + lane];
                float s1 = sc[r * 66 + 32 + lane];

                uint32_t km = __reduce_max_sync(FULL, max(fkey(s0), fkey(s1)));
                float m = funkey(km);
                float e0 = expf(s0 - m), e1 = expf(s1 - m);
                float s = e0 + e1;
                #pragma unroll
                for (int off = 16; off; off >>= 1) s += __shfl_xor_sync(FULL, s, off);
                float p0 = e0 / s, p1 = e1 / s;

                uint32_t ua = __float_as_uint(p0), uc = __float_as_uint(p1);
                uint32_t mm = 0;
                #pragma unroll
                for (int tI = 0; tI < 5; tI++) {
                    mm = __reduce_max_sync(FULL, max(ua, uc));
                    unsigned ba = __ballot_sync(FULL, ua == mm);
                    unsigned bc = __ballot_sync(FULL, uc == mm);
                    if (ba) { if (lane == __ffs(ba) - 1) ua = 0; }
                    else    { if (lane == __ffs(bc) - 1) uc = 0; }
                }
                float kth = __uint_as_float(mm);

                float delta = kth + EPS_F;
                float w0 = fmaxf(p0 - delta, 0.0f);
                float w1 = fmaxf(p1 - delta, 0.0f);
                float ws = w0 + w1;
                #pragma unroll
                for (int off = 16; off; off >>= 1) ws += __shfl_xor_sync(FULL, ws, off);
                float denom = ws + EPS_F;
                w0 /= denom;
                w1 /= denom;

                if (write_attn) {
                    size_t ab = (size_t)ATTN_OFF + (((size_t)(h * BATCH + b) * 64 + r) * 64);
                    d_out[ab + lane]      = w0;
                    d_out[ab + 32 + lane] = w1;
                }

                float o0 = 0.0f, o1 = 0.0f;
                unsigned mA = __ballot_sync(FULL, w0 > 0.0f);
                unsigned mB = __ballot_sync(FULL, w1 > 0.0f);
                while (mA) {
                    int src = __ffs(mA) - 1; mA &= mA - 1;
                    float w = __shfl_sync(FULL, w0, src);
                    float2 vv = *(float2*)&vs[src * 64 + 2 * lane];
                    o0 += w * vv.x; o1 += w * vv.y;
                }
                while (mB) {
                    int src = __ffs(mB) - 1; mB &= mB - 1;
                    float w = __shfl_sync(FULL, w1, src);
                    float2 vv = *(float2*)&vs[(src + 32) * 64 + 2 * lane];
                    o0 += w * vv.x; o1 += w * vv.y;
                }
                uint32_t hh, ll;
                bsplit2(o0, o1, hh, ll);
                size_t oi = ((size_t)(b * SEQ + r)) * KPACK + h * 32 + lane;
                g_oH[oi] = hh;
                g_oL[oi] = ll;
            }
        }

        // signal completion for the out m-tile covering this batch
        __threadfence();
        __syncthreads();
        if (tid == 0) atomicAdd(&g_cnt_attn[b >> 1], 1);
        return;
    }

    // ================= fc/gate (out) role =================
    const int oidx = bid / 3;
    const int mx = oidx >> 3, oy = oidx & 7;
    const int m0 = mx * 128;
    const int o0 = oy * 64;

    // wait for the 16 attention CTAs producing rows [m0, m0+128)
    if (tid == 0) {
        volatile int* c = g_cnt_attn + mx;
        while (*c < 16) __nanosleep(128);
    }
    __syncthreads();
    __threadfence();

    const uint32_t sbase = smem_u32(dsm);
    float* bias = (float*)(dsm + 12288);

    const int warp_m = (wid & 1) * 64;
    const int warp_n = (wid >> 1) * 16;

    if (tid < 64) { bias[tid] = fc_b[o0 + tid]; bias[64 + tid] = gb[o0 + tid]; }

    const int arow = tid >> 1, ahalf = tid & 1;
    const uint32_t* aHp = g_oH + (size_t)(m0 + arow) * KPACK + ahalf * 4;
    const uint32_t* aLp = g_oL + (size_t)(m0 + arow) * KPACK + ahalf * 4;
    const uint32_t aoffH = arow * 12 + ahalf * 4;
    const int barr = tid >> 6, brow = tid & 63;
    const uint32_t* bsrc =
        (barr == 0) ? g_fH : (barr == 1) ? g_fL : (barr == 2) ? g_gH : g_gL;
    const uint32_t* bp = bsrc + (size_t)(o0 + brow) * KPACK;
    const uint32_t boff = 3072 + barr * 768 + brow * 12;

    cp16(sbase + 4 * (O_AHI(0) + aoffH), aHp);
    cp16(sbase + 4 * (O_ALO(0) + aoffH), aLp);
    cp16(sbase + 4 * (boff + 0), bp + 0);
    cp16(sbase + 4 * (boff + 4), bp + 4);
    cp_commit();
    cp_wait0();
    __syncthreads();

    float accf[4][2][4] = {};
    float accg[4][2][4] = {};

    for (int it = 0; it < 32; ++it) {
        const int cur = it & 1, nxt = cur ^ 1;
        if (it < 31) {
            const int kp0 = (it + 1) * 8;
            cp16(sbase + 4 * (O_AHI(nxt) + aoffH), aHp + kp0);
            cp16(sbase + 4 * (O_ALO(nxt) + aoffH), aLp + kp0);
            cp16(sbase + 4 * (nxt * 6144 + boff + 0), bp + kp0 + 0);
            cp16(sbase + 4 * (nxt * 6144 + boff + 4), bp + kp0 + 4);
            cp_commit();
        }

        const uint32_t* Ah = dsm + O_AHI(cur);
        const uint32_t* Al = dsm + O_ALO(cur);
        const uint32_t* Fh = dsm + O_B(cur) + 0 * 768;
        const uint32_t* Fl = dsm + O_B(cur) + 1 * 768;
        const uint32_t* Gh = dsm + O_B(cur) + 2 * 768;
        const uint32_t* Gl = dsm + O_B(cur) + 3 * 768;

        uint32_t af[4][4], bfh[2][2], bgh[2][2], bq[2][2], bp2[2][2];
        #pragma unroll
        for (int mi = 0; mi < 4; ++mi) {
            const int rb = warp_m + mi * 16;
            af[mi][0] = Ah[(rb + g)     * 12 + t];
            af[mi][1] = Ah[(rb + g + 8) * 12 + t];
            af[mi][2] = Ah[(rb + g)     * 12 + t + 4];
            af[mi][3] = Ah[(rb + g + 8) * 12 + t + 4];
        }
        #pragma unroll
        for (int ni = 0; ni < 2; ++ni) {
            const int nb = warp_n + ni * 8;
            bfh[ni][0] = Fh[(nb + g) * 12 + t];
            bfh[ni][1] = Fh[(nb + g) * 12 + t + 4];
            bgh[ni][0] = Gh[(nb + g) * 12 + t];
            bgh[ni][1] = Gh[(nb + g) * 12 + t + 4];
        }
        #pragma unroll
        for (int mi = 0; mi < 4; ++mi)
            #pragma unroll
            for (int ni = 0; ni < 2; ++ni) {
                mma_bf16(accf[mi][ni], af[mi], bfh[ni]);   // hi*hi
                mma_bf16(accg[mi][ni], af[mi], bgh[ni]);
            }

        #pragma unroll
        for (int ni = 0; ni < 2; ++ni) {
            const int nb = warp_n + ni * 8;
            bq[ni][0]  = Fl[(nb + g) * 12 + t];
            bq[ni][1]  = Fl[(nb + g) * 12 + t + 4];
            bp2[ni][0] = Gl[(nb + g) * 12 + t];
            bp2[ni][1] = Gl[(nb + g) * 12 + t + 4];
        }
        #pragma unroll
        for (int mi = 0; mi < 4; ++mi)
            #pragma unroll
            for (int ni = 0; ni < 2; ++ni) {
                mma_bf16(accf[mi][ni], af[mi], bq[ni]);    // hi*lo
                mma_bf16(accg[mi][ni], af[mi], bp2[ni]);
            }

        #pragma unroll
        for (int mi = 0; mi < 4; ++mi) {
            const int rb = warp_m + mi * 16;
            af[mi][0] = Al[(rb + g)     * 12 + t];
            af[mi][1] = Al[(rb + g + 8) * 12 + t];
            af[mi][2] = Al[(rb + g)     * 12 + t + 4];
            af[mi][3] = Al[(rb + g + 8) * 12 + t + 4];
        }
        #pragma unroll
        for (int mi = 0; mi < 4; ++mi)
            #pragma unroll
            for (int ni = 0; ni < 2; ++ni) {
                mma_bf16(accf[mi][ni], af[mi], bfh[ni]);   // lo*hi
                mma_bf16(accg[mi][ni], af[mi], bgh[ni]);
            }

        if (it < 31) cp_wait0();
        __syncthreads();
    }

    #pragma unroll
    for (int mi = 0; mi < 4; ++mi) {
        const int r0 = m0 + warp_m + mi * 16 + g;
        #pragma unroll
        for (int ni = 0; ni < 2; ++ni) {
            const int lc = warp_n + ni * 8 + 2 * t;
            const int c0 = o0 + lc;
            #pragma unroll
            for (int half = 0; half < 2; ++half) {
                const int row = r0 + half * 8;
                float f0 = accf[mi][ni][half * 2 + 0] + bias[lc];
                float f1 = accf[mi][ni][half * 2 + 1] + bias[lc + 1];
                float g0 = accg[mi][ni][half * 2 + 0] + bias[64 + lc];
                float g1 = accg[mi][ni][half * 2 + 1] + bias[64 + lc + 1];
                float s0 = 1.0f / (1.0f + expf(-g0));
                float s1 = 1.0f / (1.0f + expf(-g1));
                *(float2*)(d_out + (size_t)row * DMODEL + c0) =
                    make_float2(s0 * tanhf(f0), s1 * tanhf(f1));
            }
        }
    }

    if (write_scalar && mx == 0 && oy == 0 && tid == 0)
        d_out[SCALAR_OFF] = 0.0f;
}

// ---------------------------------------------------------------------------
extern "C" void kernel_launch(void* const* d_in, const int* in_sizes, int n_in,
                              void* d_out, int out_size)
{
    const float* q      = (const float*)d_in[0];
    const float* k      = (const float*)d_in[1];
    const float* v      = (const float*)d_in[2];
    const float* Wq     = (const float*)d_in[3];
    const float* Wk     = (const float*)d_in[4];
    const float* Wv     = (const float*)d_in[5];
    const float* fc_w   = (const float*)d_in[6];
    const float* fc_b   = (const float*)d_in[7];
    const float* gate_w = (const float*)d_in[8];
    const float* gate_b = (const float*)d_in[9];
    float* out = (float*)d_out;

    const int write_attn   = (out_size >= ATTN_OFF + ATTN_ELEMS) ? 1 : 0;
    const int write_scalar = (out_size >= SCALAR_OFF + 1) ? 1 : 0;

    static int configured = 0;
    if (!configured) {
        cudaFuncSetAttribute(attn_out, cudaFuncAttributeMaxDynamicSharedMemorySize, AT_BYTES);
        configured = 1;
    }

    proj_pack<<<2048, 256>>>(q, k, v, Wq, Wk, Wv, fc_w, gate_w);

    attn_out<<<3072, 256, AT_BYTES>>>(fc_b, gate_b, out, write_attn, write_scalar);
}

// round 17
// speedup vs baseline: 1.8656x; 1.8656x over previous
#include <cuda_runtime.h>
#include <cuda_bf16.h>
#include <cstdint>
#include <math.h>

#define BATCH  256
#define SEQ    64
#define DMODEL 512
#define HDIM   512
#define NHEAD  8
#define DK     64
#define EPS_F  1e-7f

#define OUT_ELEMS  (BATCH * SEQ * DMODEL)          // 8388608
#define ATTN_ELEMS (NHEAD * BATCH * SEQ * SEQ)     // 8388608
#define ATTN_OFF   OUT_ELEMS
#define SCALAR_OFF (OUT_ELEMS + ATTN_ELEMS)

#define NROWS  (BATCH * SEQ)   // 16384
#define KPACK  256             // packed bf16x2 pairs per 512-wide row
#define UF     (DMODEL * KPACK / 2)   // 65536 float4-units per weight tensor

// Scratch (device globals; allocation-free per harness rules)
__device__ float    g_vh[NROWS * HDIM];       // V projection (fp32, for sparse P.V)
__device__ uint32_t g_qH[NROWS * KPACK];      // packed Q projection (hi)
__device__ uint32_t g_qL[NROWS * KPACK];
__device__ uint32_t g_kH[NROWS * KPACK];      // packed K projection
__device__ uint32_t g_kL[NROWS * KPACK];
__device__ uint32_t g_oH[NROWS * KPACK];      // packed attention output
__device__ uint32_t g_oL[NROWS * KPACK];
__device__ uint32_t g_fH[DMODEL * KPACK];     // packed fc_w
__device__ uint32_t g_fL[DMODEL * KPACK];
__device__ uint32_t g_gH[DMODEL * KPACK];     // packed gate_w
__device__ uint32_t g_gL[DMODEL * KPACK];

// ---------------------------------------------------------------------------
// Helpers
// ---------------------------------------------------------------------------
__device__ __forceinline__ void bsplit2(float x, float y, uint32_t& h, uint32_t& l) {
    __nv_bfloat162 hp = __floats2bfloat162_rn(x, y);
    float lx = x - __low2float(hp);
    float ly = y - __high2float(hp);
    __nv_bfloat162 lp = __floats2bfloat162_rn(lx, ly);
    h = *reinterpret_cast<uint32_t*>(&hp);
    l = *reinterpret_cast<uint32_t*>(&lp);
}
__device__ __forceinline__ void mma_bf16(float* c, const uint32_t* a, const uint32_t* b) {
    asm volatile(
        "mma.sync.aligned.m16n8k16.row.col.f32.bf16.bf16.f32 "
        "{%0,%1,%2,%3}, {%4,%5,%6,%7}, {%8,%9}, {%0,%1,%2,%3};"
        : "+f"(c[0]), "+f"(c[1]), "+f"(c[2]), "+f"(c[3])
        : "r"(a[0]), "r"(a[1]), "r"(a[2]), "r"(a[3]), "r"(b[0]), "r"(b[1]));
}
__device__ __forceinline__ uint32_t smem_u32(const void* p) {
    uint32_t a;
    asm("{ .reg .u64 t; cvta.to.shared.u64 t, %1; cvt.u32.u64 %0, t; }" : "=r"(a) : "l"(p));
    return a;
}
__device__ __forceinline__ void cp16(uint32_t s, const void* g) {
    asm volatile("cp.async.cg.shared.global [%0], [%1], 16;" :: "r"(s), "l"(g));
}
__device__ __forceinline__ void cp_commit() { asm volatile("cp.async.commit_group;"); }
__device__ __forceinline__ void cp_wait0()  { asm volatile("cp.async.wait_group 0;"); }

// Order-preserving integer key for arbitrary-sign floats (no NaN in data)
__device__ __forceinline__ uint32_t fkey(float f) {
    uint32_t b = __float_as_uint(f);
    return b ^ (uint32_t)(((int32_t)b >> 31) | 0x80000000);
}
__device__ __forceinline__ float funkey(uint32_t k) {
    uint32_t b = (k & 0x80000000u) ? (k ^ 0x80000000u) : ~k;
    return __uint_as_float(b);
}

#define PA   12    // packed A pitch (uint32): frag bank 12g+t conflict-free
#define PBP  136   // proj B [kp][o] pitch: frag bank 8t+g conflict-free

// ---------------------------------------------------------------------------
// Kernel A: group-linear projections + weight-pack tail CTAs (R14, 296us).
//   bid < 1536: proj tile; bid >= 1536: fc/gate weight pack.
// grid = 2048, block = 256
// ---------------------------------------------------------------------------
__global__ __launch_bounds__(256, 2) void proj_pack(
    const float* __restrict__ q, const float* __restrict__ kin, const float* __restrict__ v,
    const float* __restrict__ Wq, const float* __restrict__ Wk, const float* __restrict__ Wv,
    const float* __restrict__ fw, const float* __restrict__ gww)
{
    __shared__ __align__(16) uint32_t Ahi[128 * PA], Alo[128 * PA];   // [m][kpair]
    __shared__ __align__(16) uint32_t Bhi[8 * PBP],  Blo[8 * PBP];    // [kpair][o]

    const int bid = blockIdx.x;
    const int tid = threadIdx.x;

    if (bid >= 1536) {   // weight-pack role: 512 blocks cover 2*UF float4 units
        int gid = (bid - 1536) * 256 + tid;
        const float* src; uint32_t* H; uint32_t* L; int off;
        if (gid < UF) { src = fw;  H = g_fH; L = g_fL; off = gid; }
        else          { src = gww; H = g_gH; L = g_gL; off = gid - UF; }
        float4 f = ((const float4*)src)[off];
        uint2 h, l;
        bsplit2(f.x, f.y, h.x, l.x);
        bsplit2(f.z, f.w, h.y, l.y);
        ((uint2*)H)[off] = h;
        ((uint2*)L)[off] = l;
        return;
    }

    const int m0 = (bid & 1) * 128;
    const int t2 = bid >> 1;
    const int o0 = (t2 & 3) * 128;
    const int z  = t2 >> 2;
    const int proj = z >> 6, n = z & 63;
    const float* X; const float* W;
    if (proj == 0)      { X = q;   W = Wq; }
    else if (proj == 1) { X = kin; W = Wk; }
    else                { X = v;   W = Wv; }

    const int lane = tid & 31;
    const int wid  = tid >> 5;
    const int g    = lane >> 2;
    const int t    = lane & 3;
    const int warp_m = (wid & 1) * 64;
    const int warp_n = (wid >> 1) * 32;

    const int ar = tid >> 1, sA = (tid & 1);
    const int kp = tid >> 5, og = lane * 4;

    float acc[4][4][4] = {};

    for (int it = 0; it < 32; ++it) {
        const int k0 = it * 16;

        {
            const float* ap = X + (size_t)(m0 + ar) * (SEQ * DMODEL) + (size_t)n * DMODEL + k0 + sA * 8;
            float4 f0 = *(const float4*)ap;
            float4 f1 = *(const float4*)(ap + 4);
            uint4 H, L;
            bsplit2(f0.x, f0.y, H.x, L.x);
            bsplit2(f0.z, f0.w, H.y, L.y);
            bsplit2(f1.x, f1.y, H.z, L.z);
            bsplit2(f1.z, f1.w, H.w, L.w);
            *(uint4*)&Ahi[ar * PA + sA * 4] = H;
            *(uint4*)&Alo[ar * PA + sA * 4] = L;
        }
        {
            const float* bp = W + (size_t)n * (DMODEL * HDIM) + (size_t)(k0 + 2 * kp) * HDIM + o0 + og;
            float4 f0 = *(const float4*)bp;
            float4 f1 = *(const float4*)(bp + HDIM);
            uint4 H, L;
            bsplit2(f0.x, f1.x, H.x, L.x);
            bsplit2(f0.y, f1.y, H.y, L.y);
            bsplit2(f0.z, f1.z, H.z, L.z);
            bsplit2(f0.w, f1.w, H.w, L.w);
            *(uint4*)&Bhi[kp * PBP + og] = H;
            *(uint4*)&Blo[kp * PBP + og] = L;
        }
        __syncthreads();

        uint32_t af[4][4], bh[4][2], bx[4][2];
        #pragma unroll
        for (int mi = 0; mi < 4; ++mi) {
            const int rb = warp_m + mi * 16;
            af[mi][0] = Ahi[(rb + g)     * PA + t];
            af[mi][1] = Ahi[(rb + g + 8) * PA + t];
            af[mi][2] = Ahi[(rb + g)     * PA + t + 4];
            af[mi][3] = Ahi[(rb + g + 8) * PA + t + 4];
        }
        #pragma unroll
        for (int ni = 0; ni < 4; ++ni) {
            const int nb = warp_n + ni * 8;
            bh[ni][0] = Bhi[t       * PBP + nb + g];
            bh[ni][1] = Bhi[(t + 4) * PBP + nb + g];
        }
        #pragma unroll
        for (int mi = 0; mi < 4; ++mi)
            #pragma unroll
            for (int ni = 0; ni < 4; ++ni)
                mma_bf16(acc[mi][ni], af[mi], bh[ni]);    // hi*hi

        #pragma unroll
        for (int ni = 0; ni < 4; ++ni) {
            const int nb = warp_n + ni * 8;
            bx[ni][0] = Blo[t       * PBP + nb + g];
            bx[ni][1] = Blo[(t + 4) * PBP + nb + g];
        }
        #pragma unroll
        for (int mi = 0; mi < 4; ++mi)
            #pragma unroll
            for (int ni = 0; ni < 4; ++ni)
                mma_bf16(acc[mi][ni], af[mi], bx[ni]);    // hi*lo

        #pragma unroll
        for (int mi = 0; mi < 4; ++mi) {
            const int rb = warp_m + mi * 16;
            af[mi][0] = Alo[(rb + g)     * PA + t];
            af[mi][1] = Alo[(rb + g + 8) * PA + t];
            af[mi][2] = Alo[(rb + g)     * PA + t + 4];
            af[mi][3] = Alo[(rb + g + 8) * PA + t + 4];
        }
        #pragma unroll
        for (int mi = 0; mi < 4; ++mi)
            #pragma unroll
            for (int ni = 0; ni < 4; ++ni)
                mma_bf16(acc[mi][ni], af[mi], bh[ni]);    // lo*hi

        __syncthreads();
    }

    if (proj < 2) {
        uint32_t* YH = (proj == 0) ? g_qH : g_kH;
        uint32_t* YL = (proj == 0) ? g_qL : g_kL;
        #pragma unroll
        for (int mi = 0; mi < 4; ++mi) {
            const int r0 = m0 + warp_m + mi * 16 + g;
            #pragma unroll
            for (int ni = 0; ni < 4; ++ni) {
                const int pi = (o0 + warp_n + ni * 8 + 2 * t) >> 1;
                uint32_t h0, l0, h1, l1;
                bsplit2(acc[mi][ni][0], acc[mi][ni][1], h0, l0);
                bsplit2(acc[mi][ni][2], acc[mi][ni][3], h1, l1);
                YH[((size_t)r0 * SEQ + n) * KPACK + pi] = h0;
                YL[((size_t)r0 * SEQ + n) * KPACK + pi] = l0;
                YH[((size_t)(r0 + 8) * SEQ + n) * KPACK + pi] = h1;
                YL[((size_t)(r0 + 8) * SEQ + n) * KPACK + pi] = l1;
            }
        }
    } else {
        #pragma unroll
        for (int mi = 0; mi < 4; ++mi) {
            const int r0 = m0 + warp_m + mi * 16 + g;
            #pragma unroll
            for (int ni = 0; ni < 4; ++ni) {
                const int c0 = o0 + warp_n + ni * 8 + 2 * t;
                *(float2*)(g_vh + ((size_t)r0 * SEQ + n) * HDIM + c0) =
                    make_float2(acc[mi][ni][0], acc[mi][ni][1]);
                *(float2*)(g_vh + ((size_t)(r0 + 8) * SEQ + n) * HDIM + c0) =
                    make_float2(acc[mi][ni][2], acc[mi][ni][3]);
            }
        }
    }
}

// ---------------------------------------------------------------------------
// Kernel B: attention per (b, h). Slim smem (SC aliases Q/K), 3 CTAs/SM.
//   Softmax phase fully unrolled across the warp's 8 rows (independent
//   redux/exp/shfl chains pipeline); then top-5 + sparse P.V (unroll 2).
// grid = 2048, block = 256, dyn smem 53248 B
// ---------------------------------------------------------------------------
#define AT_SC  0       // fp32 64x66, aliases QH/QL after S computed
#define AT_QH  0
#define AT_QL  2304
#define AT_KH  4608
#define AT_KL  6912
#define AT_V   9216    // fp32 region, 64x64
#define AT_U32 13312
#define AT_BYTES (AT_U32 * 4)
#define QPITCH 36

__global__ __launch_bounds__(256, 3) void attn_mma(
    float* __restrict__ d_out, int write_attn)
{
    extern __shared__ uint32_t dsm[];

    const int bid = blockIdx.x;
    const int tid = threadIdx.x;
    const int b  = bid >> 3;
    const int h  = bid & 7;

    const int lane = tid & 31;
    const int wid  = tid >> 5;
    const int g    = lane >> 2;
    const int t    = lane & 3;

    // ---- Load packed Q/K + fp32 V ----
    {
        const int arr = tid >> 6, row = tid & 63;
        const uint32_t* src =
            ((arr == 0) ? g_qH : (arr == 1) ? g_qL : (arr == 2) ? g_kH : g_kL)
            + ((size_t)(b * SEQ + row)) * KPACK + h * 32;
        uint32_t* dst = dsm + ((arr == 0) ? AT_QH : (arr == 1) ? AT_QL
                               : (arr == 2) ? AT_KH : AT_KL) + row * QPITCH;
        #pragma unroll
        for (int i = 0; i < 8; ++i)
            *(uint4*)(dst + i * 4) = *(const uint4*)(src + i * 4);
    }
    {
        float* vs = (float*)(dsm + AT_V);
        const int vrow = tid >> 2, vq = tid & 3;
        const float* src = g_vh + ((size_t)(b * SEQ + vrow)) * HDIM + h * DK + vq * 16;
        #pragma unroll
        for (int i = 0; i < 4; ++i)
            *(float4*)&vs[vrow * 64 + vq * 16 + i * 4] = *(const float4*)(src + i * 4);
    }
    __syncthreads();

    // ---- S = Q.K^T / 8 via 3-MMA bf16 split (acc in registers) ----
    float acc[4][4] = {};
    const int mb  = (wid >> 1) * 16;
    const int nb0 = (wid & 1) * 32;
    {
        const uint32_t* Qh = dsm + AT_QH;
        const uint32_t* Ql = dsm + AT_QL;
        const uint32_t* Kh = dsm + AT_KH;
        const uint32_t* Kl = dsm + AT_KL;

        #pragma unroll
        for (int c = 0; c < 4; ++c) {
            const int co = c * 8;
            uint32_t aH[4], aL[4], bh[4][2], bl[4][2];
            aH[0] = Qh[(mb + g)     * QPITCH + co + t];
            aH[1] = Qh[(mb + g + 8) * QPITCH + co + t];
            aH[2] = Qh[(mb + g)     * QPITCH + co + t + 4];
            aH[3] = Qh[(mb + g + 8) * QPITCH + co + t + 4];
            aL[0] = Ql[(mb + g)     * QPITCH + co + t];
            aL[1] = Ql[(mb + g + 8) * QPITCH + co + t];
            aL[2] = Ql[(mb + g)     * QPITCH + co + t + 4];
            aL[3] = Ql[(mb + g + 8) * QPITCH + co + t + 4];
            #pragma unroll
            for (int ni = 0; ni < 4; ++ni) {
                const int nb = nb0 + ni * 8;
                bh[ni][0] = Kh[(nb + g) * QPITCH + co + t];
                bh[ni][1] = Kh[(nb + g) * QPITCH + co + t + 4];
                bl[ni][0] = Kl[(nb + g) * QPITCH + co + t];
                bl[ni][1] = Kl[(nb + g) * QPITCH + co + t + 4];
            }
            #pragma unroll
            for (int ni = 0; ni < 4; ++ni) {
                mma_bf16(acc[ni], aH, bh[ni]);   // hi*hi
                mma_bf16(acc[ni], aH, bl[ni]);   // hi*lo
                mma_bf16(acc[ni], aL, bh[ni]);   // lo*hi
            }
        }
    }
    __syncthreads();   // all warps done READING Q/K -> safe to alias SC over it

    {
        float* sc = (float*)(dsm + AT_SC);
        #pragma unroll
        for (int ni = 0; ni < 4; ++ni) {
            const int nb = nb0 + ni * 8;
            *(float2*)&sc[(mb + g) * 66 + nb + 2 * t] =
                make_float2(acc[ni][0] * 0.125f, acc[ni][1] * 0.125f);
            *(float2*)&sc[(mb + g + 8) * 66 + nb + 2 * t] =
                make_float2(acc[ni][2] * 0.125f, acc[ni][3] * 0.125f);
        }
    }
    __syncthreads();

    {
        float* sc = (float*)(dsm + AT_SC);
        float* vs = (float*)(dsm + AT_V);
        const unsigned FULL = 0xffffffffu;

        // Phase A: softmax for all 8 rows, fully unrolled (8 independent chains)
        float p0v[8], p1v[8];
        #pragma unroll
        for (int rr = 0; rr < 8; rr++) {
            int r = wid * 8 + rr;
            float s0 = sc[r * 66 + lane];
            float s1 = sc[r * 66 + 32 + lane];
            uint32_t km = __reduce_max_sync(FULL, max(fkey(s0), fkey(s1)));
            float m = funkey(km);
            float e0 = __expf(s0 - m), e1 = __expf(s1 - m);
            float s = e0 + e1;
            #pragma unroll
            for (int off = 16; off; off >>= 1) s += __shfl_xor_sync(FULL, s, off);
            float inv = __fdividef(1.0f, s);
            p0v[rr] = e0 * inv;
            p1v[rr] = e1 * inv;
        }

        // Phase B: top-5 + renorm + sparse P.V per row (unroll 2 for overlap)
        #pragma unroll 2
        for (int rr = 0; rr < 8; rr++) {
            int r = wid * 8 + rr;
            float p0 = p0v[rr], p1 = p1v[rr];

            uint32_t ua = __float_as_uint(p0), uc = __float_as_uint(p1);
            uint32_t mm = 0;
            #pragma unroll
            for (int tI = 0; tI < 5; tI++) {
                mm = __reduce_max_sync(FULL, max(ua, uc));
                unsigned ba = __ballot_sync(FULL, ua == mm);
                unsigned bc = __ballot_sync(FULL, uc == mm);
                if (ba) { if (lane == __ffs(ba) - 1) ua = 0; }
                else    { if (lane == __ffs(bc) - 1) uc = 0; }
            }
            float kth = __uint_as_float(mm);

            float delta = kth + EPS_F;
            float w0 = fmaxf(p0 - delta, 0.0f);
            float w1 = fmaxf(p1 - delta, 0.0f);
            float ws = w0 + w1;
            #pragma unroll
            for (int off = 16; off; off >>= 1) ws += __shfl_xor_sync(FULL, ws, off);
            float inv = __fdividef(1.0f, ws + EPS_F);
            w0 *= inv;
            w1 *= inv;

            if (write_attn) {
                size_t ab = (size_t)ATTN_OFF + (((size_t)(h * BATCH + b) * 64 + r) * 64);
                d_out[ab + lane]      = w0;
                d_out[ab + 32 + lane] = w1;
            }

            float o0 = 0.0f, o1 = 0.0f;
            unsigned mA = __ballot_sync(FULL, w0 > 0.0f);
            unsigned mB = __ballot_sync(FULL, w1 > 0.0f);
            while (mA) {
                int src = __ffs(mA) - 1; mA &= mA - 1;
                float w = __shfl_sync(FULL, w0, src);
                float2 vv = *(float2*)&vs[src * 64 + 2 * lane];
                o0 += w * vv.x; o1 += w * vv.y;
            }
            while (mB) {
                int src = __ffs(mB) - 1; mB &= mB - 1;
                float w = __shfl_sync(FULL, w1, src);
                float2 vv = *(float2*)&vs[(src + 32) * 64 + 2 * lane];
                o0 += w * vv.x; o1 += w * vv.y;
            }
            uint32_t hh, ll;
            bsplit2(o0, o1, hh, ll);
            size_t oi = ((size_t)(b * SEQ + r)) * KPACK + h * 32 + lane;
            g_oH[oi] = hh;
            g_oL[oi] = ll;
        }
    }
}

// ---------------------------------------------------------------------------
// Kernel C: fc + gate, prepacked operands via cp.async (R7/R11: ~200us).
// grid = (128, 8), block = 256, dyn smem 49152 B
// ---------------------------------------------------------------------------
#define O_AHI(b) ((b) * 6144 + 0)
#define O_ALO(b) ((b) * 6144 + 1536)
#define O_B(b)   ((b) * 6144 + 3072)
#define O_SMEM   (2 * 6144 * 4)

__global__ __launch_bounds__(256, 2) void out_mma(
    const float* __restrict__ fc_b, const float* __restrict__ gb,
    float* __restrict__ d_out, int write_scalar)
{
    extern __shared__ uint32_t dsm[];
    const uint32_t sbase = smem_u32(dsm);
    __shared__ float sbf[64], sbg[64];

    const int m0 = blockIdx.x * 128;
    const int o0 = blockIdx.y * 64;

    const int tid  = threadIdx.x;
    const int lane = tid & 31;
    const int wid  = tid >> 5;
    const int g    = lane >> 2;
    const int t    = lane & 3;
    const int warp_m = (wid & 1) * 64;
    const int warp_n = (wid >> 1) * 16;

    if (tid < 64) { sbf[tid] = fc_b[o0 + tid]; sbg[tid] = gb[o0 + tid]; }

    const int arow = tid >> 1, ahalf = tid & 1;
    const uint32_t* aHp = g_oH + (size_t)(m0 + arow) * KPACK + ahalf * 4;
    const uint32_t* aLp = g_oL + (size_t)(m0 + arow) * KPACK + ahalf * 4;
    const uint32_t aoffH = arow * 12 + ahalf * 4;
    const int barr = tid >> 6, brow = tid & 63;
    const uint32_t* bsrc =
        (barr == 0) ? g_fH : (barr == 1) ? g_fL : (barr == 2) ? g_gH : g_gL;
    const uint32_t* bp = bsrc + (size_t)(o0 + brow) * KPACK;
    const uint32_t boff = 3072 + barr * 768 + brow * 12;

    cp16(sbase + 4 * (O_AHI(0) + aoffH), aHp);
    cp16(sbase + 4 * (O_ALO(0) + aoffH), aLp);
    cp16(sbase + 4 * (boff + 0), bp + 0);
    cp16(sbase + 4 * (boff + 4), bp + 4);
    cp_commit();
    cp_wait0();
    __syncthreads();

    float accf[4][2][4] = {};
    float accg[4][2][4] = {};

    for (int it = 0; it < 32; ++it) {
        const int cur = it & 1, nxt = cur ^ 1;
        if (it < 31) {
            const int kp0 = (it + 1) * 8;
            cp16(sbase + 4 * (O_AHI(nxt) + aoffH), aHp + kp0);
            cp16(sbase + 4 * (O_ALO(nxt) + aoffH), aLp + kp0);
            cp16(sbase + 4 * (nxt * 6144 + boff + 0), bp + kp0 + 0);
            cp16(sbase + 4 * (nxt * 6144 + boff + 4), bp + kp0 + 4);
            cp_commit();
        }

        const uint32_t* Ah = dsm + O_AHI(cur);
        const uint32_t* Al = dsm + O_ALO(cur);
        const uint32_t* Fh = dsm + O_B(cur) + 0 * 768;
        const uint32_t* Fl = dsm + O_B(cur) + 1 * 768;
        const uint32_t* Gh = dsm + O_B(cur) + 2 * 768;
        const uint32_t* Gl = dsm + O_B(cur) + 3 * 768;

        uint32_t af[4][4], bfh[2][2], bgh[2][2], bq[2][2], bp2[2][2];
        #pragma unroll
        for (int mi = 0; mi < 4; ++mi) {
            const int rb = warp_m + mi * 16;
            af[mi][0] = Ah[(rb + g)     * 12 + t];
            af[mi][1] = Ah[(rb + g + 8) * 12 + t];
            af[mi][2] = Ah[(rb + g)     * 12 + t + 4];
            af[mi][3] = Ah[(rb + g + 8) * 12 + t + 4];
        }
        #pragma unroll
        for (int ni = 0; ni < 2; ++ni) {
            const int nb = warp_n + ni * 8;
            bfh[ni][0] = Fh[(nb + g) * 12 + t];
            bfh[ni][1] = Fh[(nb + g) * 12 + t + 4];
            bgh[ni][0] = Gh[(nb + g) * 12 + t];
            bgh[ni][1] = Gh[(nb + g) * 12 + t + 4];
        }
        #pragma unroll
        for (int mi = 0; mi < 4; ++mi)
            #pragma unroll
            for (int ni = 0; ni < 2; ++ni) {
                mma_bf16(accf[mi][ni], af[mi], bfh[ni]);   // hi*hi
                mma_bf16(accg[mi][ni], af[mi], bgh[ni]);
            }

        #pragma unroll
        for (int ni = 0; ni < 2; ++ni) {
            const int nb = warp_n + ni * 8;
            bq[ni][0]  = Fl[(nb + g) * 12 + t];
            bq[ni][1]  = Fl[(nb + g) * 12 + t + 4];
            bp2[ni][0] = Gl[(nb + g) * 12 + t];
            bp2[ni][1] = Gl[(nb + g) * 12 + t + 4];
        }
        #pragma unroll
        for (int mi = 0; mi < 4; ++mi)
            #pragma unroll
            for (int ni = 0; ni < 2; ++ni) {
                mma_bf16(accf[mi][ni], af[mi], bq[ni]);    // hi*lo
                mma_bf16(accg[mi][ni], af[mi], bp2[ni]);
            }

        #pragma unroll
        for (int mi = 0; mi < 4; ++mi) {
            const int rb = warp_m + mi * 16;
            af[mi][0] = Al[(rb + g)     * 12 + t];
            af[mi][1] = Al[(rb + g + 8) * 12 + t];
            af[mi][2] = Al[(rb + g)     * 12 + t + 4];
            af[mi][3] = Al[(rb + g + 8) * 12 + t + 4];
        }
        #pragma unroll
        for (int mi = 0; mi < 4; ++mi)
            #pragma unroll
            for (int ni = 0; ni < 2; ++ni) {
                mma_bf16(accf[mi][ni], af[mi], bfh[ni]);   // lo*hi
                mma_bf16(accg[mi][ni], af[mi], bgh[ni]);
            }

        if (it < 31) cp_wait0();
        __syncthreads();
    }

    #pragma unroll
    for (int mi = 0; mi < 4; ++mi) {
        const int r0 = m0 + warp_m + mi * 16 + g;
        #pragma unroll
        for (int ni = 0; ni < 2; ++ni) {
            const int lc = warp_n + ni * 8 + 2 * t;
            const int c0 = o0 + lc;
            #pragma unroll
            for (int half = 0; half < 2; ++half) {
                const int row = r0 + half * 8;
                float f0 = accf[mi][ni][half * 2 + 0] + sbf[lc];
                float f1 = accf[mi][ni][half * 2 + 1] + sbf[lc + 1];
                float g0 = accg[mi][ni][half * 2 + 0] + sbg[lc];
                float g1 = accg[mi][ni][half * 2 + 1] + sbg[lc + 1];
                float s0 = 1.0f / (1.0f + expf(-g0));
                float s1 = 1.0f / (1.0f + expf(-g1));
                *(float2*)(d_out + (size_t)row * DMODEL + c0) =
                    make_float2(s0 * tanhf(f0), s1 * tanhf(f1));
            }
        }
    }

    if (write_scalar && blockIdx.x == 0 && blockIdx.y == 0 && tid == 0)
        d_out[SCALAR_OFF] = 0.0f;
}

// ---------------------------------------------------------------------------
extern "C" void kernel_launch(void* const* d_in, const int* in_sizes, int n_in,
                              void* d_out, int out_size)
{
    const float* q      = (const float*)d_in[0];
    const float* k      = (const float*)d_in[1];
    const float* v      = (const float*)d_in[2];
    const float* Wq     = (const float*)d_in[3];
    const float* Wk     = (const float*)d_in[4];
    const float* Wv     = (const float*)d_in[5];
    const float* fc_w   = (const float*)d_in[6];
    const float* fc_b   = (const float*)d_in[7];
    const float* gate_w = (const float*)d_in[8];
    const float* gate_b = (const float*)d_in[9];
    float* out = (float*)d_out;

    const int write_attn   = (out_size >= ATTN_OFF + ATTN_ELEMS) ? 1 : 0;
    const int write_scalar = (out_size >= SCALAR_OFF + 1) ? 1 : 0;

    static int configured = 0;
    if (!configured) {
        cudaFuncSetAttribute(attn_mma, cudaFuncAttributeMaxDynamicSharedMemorySize, AT_BYTES);
        cudaFuncSetAttribute(out_mma,  cudaFuncAttributeMaxDynamicSharedMemorySize, O_SMEM);
        configured = 1;
    }

    proj_pack<<<2048, 256>>>(q, k, v, Wq, Wk, Wv, fc_w, gate_w);

    attn_mma<<<2048, 256, AT_BYTES>>>(out, write_attn);

    dim3 gC(128, 8);
    out_mma<<<gC, 256, O_SMEM>>>(fc_b, gate_b, out, write_scalar);
}